// round 4
// baseline (speedup 1.0000x reference)
#include <cuda_runtime.h>
#include <math.h>

#define BB 8
#define EE 50000
#define DD 128
#define NN 10000

// ---------------- scratch ----------------
__device__ float g_dmean[BB*DD];   // per-batch per-feature SUM (scale by 1/E at use)
__device__ int   g_hist[BB*NN];    // segment counts
__device__ int   g_off [BB*NN];    // exclusive prefix
__device__ int   g_cur [BB*NN];    // scatter cursors (seeded = g_off)
__device__ int   g_perm[BB*EE];    // element ids sorted by segment

// ---------------- init ----------------
__global__ void k_init() {
    int i = blockIdx.x * blockDim.x + threadIdx.x;
    if (i < BB*NN) g_hist[i] = 0;
    if (i < BB*DD) g_dmean[i] = 0.f;
}

// ---------------- histogram (idx only) ----------------
__global__ void k_hist(const int* __restrict__ idx) {
    int i = blockIdx.x * blockDim.x + threadIdx.x;
    if (i >= BB*EE) return;
    int b = i / EE;
    atomicAdd(&g_hist[b*NN + idx[i]], 1);
}

// ---------------- per-batch exclusive scan (1 block/batch, warp-shuffle) ----------------
__global__ void k_scan() {
    __shared__ int wsum[32];
    const int CH = (NN + 1023) / 1024;   // 10
    int b = blockIdx.x, t = threadIdx.x;
    int lane = t & 31, wid = t >> 5;
    int lo = t * CH, hi = min(lo + CH, NN);
    int s = 0;
    #pragma unroll
    for (int i = lo; i < hi; i++) s += g_hist[b*NN + i];
    int v = s;
    #pragma unroll
    for (int o = 1; o < 32; o <<= 1) {
        int u = __shfl_up_sync(0xffffffffu, v, o);
        if (lane >= o) v += u;
    }
    if (lane == 31) wsum[wid] = v;
    __syncthreads();
    if (wid == 0) {
        int w = wsum[lane];
        #pragma unroll
        for (int o = 1; o < 32; o <<= 1) {
            int u = __shfl_up_sync(0xffffffffu, w, o);
            if (lane >= o) w += u;
        }
        wsum[lane] = w;
    }
    __syncthreads();
    int run = v - s + ((wid > 0) ? wsum[wid-1] : 0);
    for (int i = lo; i < hi; i++) {
        int h = g_hist[b*NN + i];
        g_off[b*NN + i] = run;
        g_cur[b*NN + i] = run;
        run += h;
    }
}

// ---------------- counting-sort scatter ----------------
__global__ void k_scatter(const int* __restrict__ idx) {
    int i = blockIdx.x * blockDim.x + threadIdx.x;
    if (i >= BB*EE) return;
    int b = i / EE, e = i - b*EE;
    int pos = atomicAdd(&g_cur[b*NN + idx[i]], 1);
    g_perm[b*EE + pos] = e;
}

// ---------------- main: one warp per segment, single data pass ----------------
__global__ void __launch_bounds__(256) k_main(const float4* __restrict__ data,
                                              const float* __restrict__ betap,
                                              float* __restrict__ out) {
    int gw   = (blockIdx.x * blockDim.x + threadIdx.x) >> 5;
    int lane = threadIdx.x & 31;
    if (gw >= BB*NN) return;
    int b = gw / NN;
    int start = g_off[gw];
    int cnt   = g_hist[gw];

    float beta = *betap;

    float4 s  = make_float4(0.f,0.f,0.f,0.f);
    float4 mx = make_float4(-INFINITY,-INFINITY,-INFINITY,-INFINITY);
    float4 sq = make_float4(0.f,0.f,0.f,0.f);   // raw sum of squares
    float4 dn = make_float4(0.f,0.f,0.f,0.f);
    float4 ws = make_float4(0.f,0.f,0.f,0.f);

    const float4* rb = data + (size_t)b * EE * (DD/4);
    const int* p = g_perm + b*EE + start;

    for (int base = 0; base < cnt; base += 32) {
        int m = min(32, cnt - base);
        int e = (lane < m) ? p[base + lane] : p[base];
        for (int k = 0; k < m; k += 4) {
            int e0 = __shfl_sync(0xffffffffu, e,  k      & 31);
            int e1 = __shfl_sync(0xffffffffu, e, (k + 1) & 31);
            int e2 = __shfl_sync(0xffffffffu, e, (k + 2) & 31);
            int e3 = __shfl_sync(0xffffffffu, e, (k + 3) & 31);
            float4 v0 = __ldg(&rb[(size_t)e0 * (DD/4) + lane]);
            float4 v1 = __ldg(&rb[(size_t)e1 * (DD/4) + lane]);
            float4 v2 = __ldg(&rb[(size_t)e2 * (DD/4) + lane]);
            float4 v3 = __ldg(&rb[(size_t)e3 * (DD/4) + lane]);
            #define ACC(v) do {                                              \
                s.x += v.x; s.y += v.y; s.z += v.z; s.w += v.w;              \
                mx.x = fmaxf(mx.x, v.x); mx.y = fmaxf(mx.y, v.y);            \
                mx.z = fmaxf(mx.z, v.z); mx.w = fmaxf(mx.w, v.w);            \
                sq.x = fmaf(v.x, v.x, sq.x); sq.y = fmaf(v.y, v.y, sq.y);    \
                sq.z = fmaf(v.z, v.z, sq.z); sq.w = fmaf(v.w, v.w, sq.w);    \
                float nx = __expf(beta * v.x);                               \
                float ny = __expf(beta * v.y);                               \
                float nz = __expf(beta * v.z);                               \
                float nw = __expf(beta * v.w);                               \
                dn.x += nx; dn.y += ny; dn.z += nz; dn.w += nw;              \
                ws.x = fmaf(v.x, nx, ws.x); ws.y = fmaf(v.y, ny, ws.y);      \
                ws.z = fmaf(v.z, nz, ws.z); ws.w = fmaf(v.w, nw, ws.w);      \
            } while (0)
            ACC(v0);
            if (k + 1 < m) ACC(v1);
            if (k + 2 < m) ACC(v2);
            if (k + 3 < m) ACC(v3);
            #undef ACC
        }
    }

    float inv = 1.f / ((cnt > 0) ? (float)cnt : 1.f);
    float4 mean = make_float4(s.x*inv, s.y*inv, s.z*inv, s.w*inv);
    if (cnt == 0) mx = make_float4(0.f,0.f,0.f,0.f);
    float4 soft;
    soft.x = ws.x / ((dn.x != 0.f) ? dn.x : 1.f);
    soft.y = ws.y / ((dn.y != 0.f) ? dn.y : 1.f);
    soft.z = ws.z / ((dn.z != 0.f) ? dn.z : 1.f);
    soft.w = ws.w / ((dn.w != 0.f) ? dn.w : 1.f);

    float4* ob = reinterpret_cast<float4*>(out + (size_t)gw * (5*DD));
    ob[lane]        = s;     // sum
    ob[32  + lane]  = mx;    // max
    ob[64  + lane]  = mean;  // mean
    ob[96  + lane]  = sq;    // raw sumsq (fixed by k_fixvar)
    ob[128 + lane]  = soft;  // softmax
}

// ---------------- column mean from output sum slots ----------------
// grid (B, 8), block 256: dm_sum[b][col] += sum over n of out[b,n,col]
__global__ void __launch_bounds__(256) k_colmean(const float* __restrict__ out) {
    int b  = blockIdx.x;
    int n0 = blockIdx.y * (NN/8);
    int n1 = n0 + (NN/8);
    int col  = threadIdx.x & (DD-1);
    int half = threadIdx.x >> 7;
    float s = 0.f;
    const float* base = out + (size_t)b * NN * (5*DD);
    for (int n = n0 + half; n < n1; n += 2)
        s += base[(size_t)n * (5*DD) + col];
    __shared__ float sh[256];
    sh[threadIdx.x] = s;
    __syncthreads();
    if (half == 0)
        atomicAdd(&g_dmean[b*DD + col], sh[col] + sh[col + 128]);
}

// ---------------- epilogue: var = relu((sq - 2 dm sum + cnt dm^2)/max(cnt,1)) ----------------
__global__ void __launch_bounds__(256) k_fixvar(float* __restrict__ out) {
    int i = blockIdx.x * blockDim.x + threadIdx.x;   // one per (segment, float4-group)
    if (i >= BB*NN*32) return;
    int gw = i >> 5, lane = i & 31;
    int b = gw / NN;
    float cnt = (float)g_hist[gw];
    float inv = 1.f / fmaxf(cnt, 1.f);
    const float invE = 1.f / (float)EE;
    float4 dm = reinterpret_cast<const float4*>(g_dmean)[b*32 + lane];
    dm.x *= invE; dm.y *= invE; dm.z *= invE; dm.w *= invE;
    float4* ob = reinterpret_cast<float4*>(out + (size_t)gw * (5*DD));
    float4 s  = ob[lane];        // sum slot
    float4 sq = ob[96 + lane];   // raw sumsq
    float4 var;
    var.x = fmaxf((sq.x - 2.f*dm.x*s.x + cnt*dm.x*dm.x) * inv, 0.f);
    var.y = fmaxf((sq.y - 2.f*dm.y*s.y + cnt*dm.y*dm.y) * inv, 0.f);
    var.z = fmaxf((sq.z - 2.f*dm.z*s.z + cnt*dm.z*dm.z) * inv, 0.f);
    var.w = fmaxf((sq.w - 2.f*dm.w*s.w + cnt*dm.w*dm.w) * inv, 0.f);
    ob[96 + lane] = var;
}

// ---------------- launch ----------------
extern "C" void kernel_launch(void* const* d_in, const int* in_sizes, int n_in,
                              void* d_out, int out_size) {
    const float* data = nullptr;
    const float* beta = nullptr;
    const int*   idx  = nullptr;
    for (int i = 0; i < n_in; i++) {
        long long sz = in_sizes[i];
        if (sz == (long long)BB*EE*DD)      data = (const float*)d_in[i];
        else if (sz == (long long)BB*EE)    idx  = (const int*)d_in[i];
        else if (sz == 1 && beta == nullptr) beta = (const float*)d_in[i];
    }
    float* out = (float*)d_out;

    k_init<<<(BB*NN + 255)/256, 256>>>();
    int nbe = (BB*EE + 255)/256;
    k_hist<<<nbe, 256>>>(idx);
    k_scan<<<BB, 1024>>>();
    k_scatter<<<nbe, 256>>>(idx);
    k_main<<<(BB*NN*32 + 255)/256, 256>>>((const float4*)data, beta, out);
    k_colmean<<<dim3(BB, 8), 256>>>(out);
    k_fixvar<<<(BB*NN*32 + 255)/256, 256>>>(out);
}

// round 5
// speedup vs baseline: 1.4546x; 1.4546x over previous
#include <cuda_runtime.h>
#include <math.h>

#define BB 8
#define EE 50000
#define DD 128
#define NN 10000

// ---------------- scratch ----------------
__device__ float g_dmean[BB*DD];   // per-batch per-feature SUM (scale by 1/E at use)
__device__ int   g_hist[BB*NN];    // segment counts
__device__ int   g_off [BB*NN];    // exclusive prefix
__device__ int   g_cur [BB*NN];    // scatter cursors (seeded = g_off)
__device__ int   g_perm[BB*EE];    // element ids sorted by segment

// ---------------- fused: histogram + per-batch feature sums ----------------
// grid (ceil(E/512), B), block 256
__global__ void k_hs(const float* __restrict__ data, const int* __restrict__ idx) {
    int b  = blockIdx.y;
    int r0 = blockIdx.x * 512;
    int r1 = min(r0 + 512, EE);
    for (int e = r0 + threadIdx.x; e < r1; e += 256)
        atomicAdd(&g_hist[b*NN + idx[b*EE + e]], 1);
    int col  = threadIdx.x & (DD-1);
    int half = threadIdx.x >> 7;
    float s = 0.f;
    for (int e = r0 + half; e < r1; e += 2)
        s += data[((size_t)b*EE + e)*DD + col];
    __shared__ float sh[256];
    sh[threadIdx.x] = s;
    __syncthreads();
    if (half == 0)
        atomicAdd(&g_dmean[b*DD + col], sh[col] + sh[col + 128]);
}

// ---------------- per-batch exclusive scan (1 block/batch, warp-shuffle) ----------------
__global__ void k_scan() {
    __shared__ int wsum[32];
    const int CH = (NN + 1023) / 1024;   // 10
    int b = blockIdx.x, t = threadIdx.x;
    int lane = t & 31, wid = t >> 5;
    int lo = t * CH, hi = min(lo + CH, NN);
    int s = 0;
    #pragma unroll
    for (int i = lo; i < hi; i++) s += g_hist[b*NN + i];
    int v = s;
    #pragma unroll
    for (int o = 1; o < 32; o <<= 1) {
        int u = __shfl_up_sync(0xffffffffu, v, o);
        if (lane >= o) v += u;
    }
    if (lane == 31) wsum[wid] = v;
    __syncthreads();
    if (wid == 0) {
        int w = wsum[lane];
        #pragma unroll
        for (int o = 1; o < 32; o <<= 1) {
            int u = __shfl_up_sync(0xffffffffu, w, o);
            if (lane >= o) w += u;
        }
        wsum[lane] = w;
    }
    __syncthreads();
    int run = v - s + ((wid > 0) ? wsum[wid-1] : 0);
    for (int i = lo; i < hi; i++) {
        int h = g_hist[b*NN + i];
        g_off[b*NN + i] = run;
        g_cur[b*NN + i] = run;
        run += h;
    }
}

// ---------------- counting-sort scatter ----------------
__global__ void k_scatter(const int* __restrict__ idx) {
    int i = blockIdx.x * blockDim.x + threadIdx.x;
    if (i >= BB*EE) return;
    int b = i / EE, e = i - b*EE;
    int pos = atomicAdd(&g_cur[b*NN + idx[i]], 1);
    g_perm[b*EE + pos] = e;
}

// ---------------- main: one warp per segment, uniform perm loads, no shfl ----------------
__global__ void __launch_bounds__(256) k_main(const float4* __restrict__ data,
                                              const float* __restrict__ betap,
                                              float* __restrict__ out) {
    int gw   = (blockIdx.x * blockDim.x + threadIdx.x) >> 5;
    int lane = threadIdx.x & 31;
    if (gw >= BB*NN) return;
    int b = gw / NN;
    int start = g_off[gw];
    int cnt   = g_hist[gw];

    float beta = *betap;
    const float invE = 1.f / (float)EE;
    float4 dm = reinterpret_cast<const float4*>(g_dmean)[b*32 + lane];
    dm.x *= invE; dm.y *= invE; dm.z *= invE; dm.w *= invE;

    float4 s  = make_float4(0.f,0.f,0.f,0.f);
    float4 mx = make_float4(-INFINITY,-INFINITY,-INFINITY,-INFINITY);
    float4 vr = make_float4(0.f,0.f,0.f,0.f);
    float4 dn = make_float4(0.f,0.f,0.f,0.f);
    float4 ws = make_float4(0.f,0.f,0.f,0.f);

    const float4* rb = data + (size_t)b * EE * (DD/4);
    const int* p = g_perm + b*EE + start;

    for (int k = 0; k < cnt; k += 4) {
        // uniform (warp-broadcast) index loads — perm is L2-resident
        int e0 = __ldg(&p[k]);
        int e1 = (k + 1 < cnt) ? __ldg(&p[k + 1]) : e0;
        int e2 = (k + 2 < cnt) ? __ldg(&p[k + 2]) : e0;
        int e3 = (k + 3 < cnt) ? __ldg(&p[k + 3]) : e0;
        float4 v0 = __ldg(&rb[(size_t)e0 * (DD/4) + lane]);
        float4 v1 = __ldg(&rb[(size_t)e1 * (DD/4) + lane]);
        float4 v2 = __ldg(&rb[(size_t)e2 * (DD/4) + lane]);
        float4 v3 = __ldg(&rb[(size_t)e3 * (DD/4) + lane]);
        #define ACC(v) do {                                              \
            s.x += v.x; s.y += v.y; s.z += v.z; s.w += v.w;              \
            mx.x = fmaxf(mx.x, v.x); mx.y = fmaxf(mx.y, v.y);            \
            mx.z = fmaxf(mx.z, v.z); mx.w = fmaxf(mx.w, v.w);            \
            float tx = v.x - dm.x, ty = v.y - dm.y;                      \
            float tz = v.z - dm.z, tw = v.w - dm.w;                      \
            vr.x = fmaf(tx, tx, vr.x); vr.y = fmaf(ty, ty, vr.y);        \
            vr.z = fmaf(tz, tz, vr.z); vr.w = fmaf(tw, tw, vr.w);        \
            float nx = __expf(beta * v.x);                               \
            float ny = __expf(beta * v.y);                               \
            float nz = __expf(beta * v.z);                               \
            float nw = __expf(beta * v.w);                               \
            dn.x += nx; dn.y += ny; dn.z += nz; dn.w += nw;              \
            ws.x = fmaf(v.x, nx, ws.x); ws.y = fmaf(v.y, ny, ws.y);      \
            ws.z = fmaf(v.z, nz, ws.z); ws.w = fmaf(v.w, nw, ws.w);      \
        } while (0)
        ACC(v0);
        if (k + 1 < cnt) ACC(v1);
        if (k + 2 < cnt) ACC(v2);
        if (k + 3 < cnt) ACC(v3);
        #undef ACC
    }

    float inv = 1.f / ((cnt > 0) ? (float)cnt : 1.f);
    float4 mean = make_float4(s.x*inv, s.y*inv, s.z*inv, s.w*inv);
    float4 var  = make_float4(fmaxf(vr.x*inv, 0.f), fmaxf(vr.y*inv, 0.f),
                              fmaxf(vr.z*inv, 0.f), fmaxf(vr.w*inv, 0.f));
    if (cnt == 0) mx = make_float4(0.f,0.f,0.f,0.f);
    float4 soft;
    soft.x = ws.x / ((dn.x != 0.f) ? dn.x : 1.f);
    soft.y = ws.y / ((dn.y != 0.f) ? dn.y : 1.f);
    soft.z = ws.z / ((dn.z != 0.f) ? dn.z : 1.f);
    soft.w = ws.w / ((dn.w != 0.f) ? dn.w : 1.f);

    float4* ob = reinterpret_cast<float4*>(out + (size_t)gw * (5*DD));
    ob[lane]        = s;     // sum
    ob[32  + lane]  = mx;    // max
    ob[64  + lane]  = mean;  // mean
    ob[96  + lane]  = var;   // var
    ob[128 + lane]  = soft;  // softmax
}

// ---------------- launch ----------------
extern "C" void kernel_launch(void* const* d_in, const int* in_sizes, int n_in,
                              void* d_out, int out_size) {
    const float* data = nullptr;
    const float* beta = nullptr;
    const int*   idx  = nullptr;
    for (int i = 0; i < n_in; i++) {
        long long sz = in_sizes[i];
        if (sz == (long long)BB*EE*DD)      data = (const float*)d_in[i];
        else if (sz == (long long)BB*EE)    idx  = (const int*)d_in[i];
        else if (sz == 1 && beta == nullptr) beta = (const float*)d_in[i];
    }
    float* out = (float*)d_out;

    // zero scratch via memset nodes (not kernel launches)
    void* p_hist = nullptr; void* p_dmean = nullptr;
    cudaGetSymbolAddress(&p_hist,  g_hist);
    cudaGetSymbolAddress(&p_dmean, g_dmean);
    cudaMemsetAsync(p_hist,  0, BB*NN*sizeof(int));
    cudaMemsetAsync(p_dmean, 0, BB*DD*sizeof(float));

    dim3 gs((EE + 511)/512, BB);
    k_hs<<<gs, 256>>>(data, idx);                              // launch 1
    k_scan<<<BB, 1024>>>();                                    // launch 2
    int nbe = (BB*EE + 255)/256;
    k_scatter<<<nbe, 256>>>(idx);                              // launch 3
    k_main<<<(BB*NN*32 + 255)/256, 256>>>((const float4*)data, beta, out);  // launch 4 (profiled)
}

// round 6
// speedup vs baseline: 1.5483x; 1.0644x over previous
#include <cuda_runtime.h>
#include <math.h>

#define BB 8
#define EE 50000
#define DD 128
#define NN 10000

// ---------------- scratch ----------------
__device__ float g_dmean[BB*DD];   // per-batch per-feature SUM (scale by 1/E at use)
__device__ int   g_hist[BB*NN];    // segment counts
__device__ int   g_off [BB*NN];    // exclusive prefix
__device__ int   g_cur [BB*NN];    // scatter cursors (seeded = g_off)
__device__ int   g_perm[BB*EE];    // element ids sorted by segment

// ---------------- fused: histogram + per-batch feature sums (float4) ----------------
// grid (ceil(E/512), B), block 256: lane c4 = float4 col, rg = row-group
__global__ void __launch_bounds__(256) k_hs(const float4* __restrict__ data,
                                            const int* __restrict__ idx) {
    int b  = blockIdx.y;
    int r0 = blockIdx.x * 512;
    int r1 = min(r0 + 512, EE);
    // histogram for this chunk of rows
    for (int e = r0 + threadIdx.x; e < r1; e += 256)
        atomicAdd(&g_hist[b*NN + idx[b*EE + e]], 1);
    // feature sums: warp reads full 512B row per access
    int c4 = threadIdx.x & 31;     // float4 column 0..31
    int rg = threadIdx.x >> 5;     // row group 0..7
    const float4* rb = data + (size_t)b * EE * 32;
    float4 s = make_float4(0.f, 0.f, 0.f, 0.f);
    for (int e = r0 + rg; e < r1; e += 8) {
        float4 v = __ldg(&rb[(size_t)e * 32 + c4]);
        s.x += v.x; s.y += v.y; s.z += v.z; s.w += v.w;
    }
    __shared__ float4 sh[256];
    sh[threadIdx.x] = s;
    __syncthreads();
    if (rg == 0) {
        #pragma unroll
        for (int j = 1; j < 8; j++) {
            float4 t = sh[c4 + 32*j];
            s.x += t.x; s.y += t.y; s.z += t.z; s.w += t.w;
        }
        float* dmb = g_dmean + b*DD + c4*4;
        atomicAdd(dmb+0, s.x); atomicAdd(dmb+1, s.y);
        atomicAdd(dmb+2, s.z); atomicAdd(dmb+3, s.w);
    }
}

// ---------------- per-batch exclusive scan (1 block/batch, warp-shuffle) ----------------
__global__ void k_scan() {
    __shared__ int wsum[32];
    const int CH = (NN + 1023) / 1024;   // 10
    int b = blockIdx.x, t = threadIdx.x;
    int lane = t & 31, wid = t >> 5;
    int lo = t * CH, hi = min(lo + CH, NN);
    int s = 0;
    #pragma unroll
    for (int i = lo; i < hi; i++) s += g_hist[b*NN + i];
    int v = s;
    #pragma unroll
    for (int o = 1; o < 32; o <<= 1) {
        int u = __shfl_up_sync(0xffffffffu, v, o);
        if (lane >= o) v += u;
    }
    if (lane == 31) wsum[wid] = v;
    __syncthreads();
    if (wid == 0) {
        int w = wsum[lane];
        #pragma unroll
        for (int o = 1; o < 32; o <<= 1) {
            int u = __shfl_up_sync(0xffffffffu, w, o);
            if (lane >= o) w += u;
        }
        wsum[lane] = w;
    }
    __syncthreads();
    int run = v - s + ((wid > 0) ? wsum[wid-1] : 0);
    for (int i = lo; i < hi; i++) {
        int h = g_hist[b*NN + i];
        g_off[b*NN + i] = run;
        g_cur[b*NN + i] = run;
        run += h;
    }
}

// ---------------- counting-sort scatter ----------------
__global__ void k_scatter(const int* __restrict__ idx) {
    int i = blockIdx.x * blockDim.x + threadIdx.x;
    if (i >= BB*EE) return;
    int b = i / EE, e = i - b*EE;
    int pos = atomicAdd(&g_cur[b*NN + idx[i]], 1);
    g_perm[b*EE + pos] = e;
}

// ---------------- main: one warp per segment, raw sq + end correction ----------------
__global__ void __launch_bounds__(256) k_main(const float4* __restrict__ data,
                                              const float* __restrict__ betap,
                                              float* __restrict__ out) {
    int gw   = (blockIdx.x * blockDim.x + threadIdx.x) >> 5;
    int lane = threadIdx.x & 31;
    if (gw >= BB*NN) return;
    int b = gw / NN;
    int start = g_off[gw];
    int cnt   = g_hist[gw];

    float beta = *betap;

    float4 s  = make_float4(0.f,0.f,0.f,0.f);
    float4 mx = make_float4(-INFINITY,-INFINITY,-INFINITY,-INFINITY);
    float4 sq = make_float4(0.f,0.f,0.f,0.f);   // raw sum of squares
    float4 dn = make_float4(0.f,0.f,0.f,0.f);
    float4 ws = make_float4(0.f,0.f,0.f,0.f);

    const float4* rb = data + (size_t)b * EE * (DD/4);
    const int* p = g_perm + b*EE + start;

    for (int k = 0; k < cnt; k += 4) {
        int e0 = __ldg(&p[k]);
        int e1 = (k + 1 < cnt) ? __ldg(&p[k + 1]) : e0;
        int e2 = (k + 2 < cnt) ? __ldg(&p[k + 2]) : e0;
        int e3 = (k + 3 < cnt) ? __ldg(&p[k + 3]) : e0;
        float4 v0 = __ldg(&rb[(size_t)e0 * (DD/4) + lane]);
        float4 v1 = __ldg(&rb[(size_t)e1 * (DD/4) + lane]);
        float4 v2 = __ldg(&rb[(size_t)e2 * (DD/4) + lane]);
        float4 v3 = __ldg(&rb[(size_t)e3 * (DD/4) + lane]);
        #define ACC(v) do {                                              \
            s.x += v.x; s.y += v.y; s.z += v.z; s.w += v.w;              \
            mx.x = fmaxf(mx.x, v.x); mx.y = fmaxf(mx.y, v.y);            \
            mx.z = fmaxf(mx.z, v.z); mx.w = fmaxf(mx.w, v.w);            \
            sq.x = fmaf(v.x, v.x, sq.x); sq.y = fmaf(v.y, v.y, sq.y);    \
            sq.z = fmaf(v.z, v.z, sq.z); sq.w = fmaf(v.w, v.w, sq.w);    \
            float nx = __expf(beta * v.x);                               \
            float ny = __expf(beta * v.y);                               \
            float nz = __expf(beta * v.z);                               \
            float nw = __expf(beta * v.w);                               \
            dn.x += nx; dn.y += ny; dn.z += nz; dn.w += nw;              \
            ws.x = fmaf(v.x, nx, ws.x); ws.y = fmaf(v.y, ny, ws.y);      \
            ws.z = fmaf(v.z, nz, ws.z); ws.w = fmaf(v.w, nw, ws.w);      \
        } while (0)
        ACC(v0);
        if (k + 1 < cnt) ACC(v1);
        if (k + 2 < cnt) ACC(v2);
        if (k + 3 < cnt) ACC(v3);
        #undef ACC
    }

    // epilogue: load dm only now (keeps hot loop lean)
    const float invE = 1.f / (float)EE;
    float4 dm = __ldg(&reinterpret_cast<const float4*>(g_dmean)[b*32 + lane]);
    dm.x *= invE; dm.y *= invE; dm.z *= invE; dm.w *= invE;

    float fcnt = (float)cnt;
    float inv  = 1.f / ((cnt > 0) ? fcnt : 1.f);
    float4 mean = make_float4(s.x*inv, s.y*inv, s.z*inv, s.w*inv);
    float4 var;
    var.x = fmaxf((sq.x - 2.f*dm.x*s.x + fcnt*dm.x*dm.x) * inv, 0.f);
    var.y = fmaxf((sq.y - 2.f*dm.y*s.y + fcnt*dm.y*dm.y) * inv, 0.f);
    var.z = fmaxf((sq.z - 2.f*dm.z*s.z + fcnt*dm.z*dm.z) * inv, 0.f);
    var.w = fmaxf((sq.w - 2.f*dm.w*s.w + fcnt*dm.w*dm.w) * inv, 0.f);
    if (cnt == 0) mx = make_float4(0.f,0.f,0.f,0.f);
    float4 soft;
    soft.x = ws.x / ((dn.x != 0.f) ? dn.x : 1.f);
    soft.y = ws.y / ((dn.y != 0.f) ? dn.y : 1.f);
    soft.z = ws.z / ((dn.z != 0.f) ? dn.z : 1.f);
    soft.w = ws.w / ((dn.w != 0.f) ? dn.w : 1.f);

    float4* ob = reinterpret_cast<float4*>(out + (size_t)gw * (5*DD));
    ob[lane]        = s;     // sum
    ob[32  + lane]  = mx;    // max
    ob[64  + lane]  = mean;  // mean
    ob[96  + lane]  = var;   // var
    ob[128 + lane]  = soft;  // softmax
}

// ---------------- launch ----------------
extern "C" void kernel_launch(void* const* d_in, const int* in_sizes, int n_in,
                              void* d_out, int out_size) {
    const float* data = nullptr;
    const float* beta = nullptr;
    const int*   idx  = nullptr;
    for (int i = 0; i < n_in; i++) {
        long long sz = in_sizes[i];
        if (sz == (long long)BB*EE*DD)      data = (const float*)d_in[i];
        else if (sz == (long long)BB*EE)    idx  = (const int*)d_in[i];
        else if (sz == 1 && beta == nullptr) beta = (const float*)d_in[i];
    }
    float* out = (float*)d_out;

    void* p_hist = nullptr; void* p_dmean = nullptr;
    cudaGetSymbolAddress(&p_hist,  g_hist);
    cudaGetSymbolAddress(&p_dmean, g_dmean);
    cudaMemsetAsync(p_hist,  0, BB*NN*sizeof(int));
    cudaMemsetAsync(p_dmean, 0, BB*DD*sizeof(float));

    dim3 gs((EE + 511)/512, BB);
    k_hs<<<gs, 256>>>((const float4*)data, idx);               // launch 1
    k_scan<<<BB, 1024>>>();                                    // launch 2
    int nbe = (BB*EE + 255)/256;
    k_scatter<<<nbe, 256>>>(idx);                              // launch 3
    k_main<<<(BB*NN*32 + 255)/256, 256>>>((const float4*)data, beta, out);  // launch 4 (profiled)
}